// round 1
// baseline (speedup 1.0000x reference)
#include <cuda_runtime.h>
#include <cuda_bf16.h>
#include <cstdint>

// ---------------- problem constants ----------------
#define HIDDEN      128
#define NUM_RADIAL  6
#define OUT_EMB     256
#define MAX_NODES   50000

// ---------------- device scratch (no allocs allowed) ----------------
__device__ float g_h[(size_t)MAX_NODES * HIDDEN];          // node accumulator [N,128]
__device__ float g_wt_up[HIDDEN * OUT_EMB];                // W_up transposed [128][256]
__device__ float g_wt_lins[3 * OUT_EMB * OUT_EMB];         // lins transposed [3][256][256]

// ---------------- f32x2 packed helpers (sm_100+) ----------------
__device__ __forceinline__ unsigned long long pack2(float a, float b) {
    unsigned long long r;
    asm("mov.b64 %0, {%1, %2};" : "=l"(r) : "f"(a), "f"(b));
    return r;
}
__device__ __forceinline__ void unpack2(unsigned long long v, float& a, float& b) {
    asm("mov.b64 {%0, %1}, %2;" : "=f"(a), "=f"(b) : "l"(v));
}
__device__ __forceinline__ void fma2(unsigned long long& d, unsigned long long a, unsigned long long b) {
    asm("fma.rn.f32x2 %0, %1, %2, %0;" : "+l"(d) : "l"(a), "l"(b));
}

// ---------------- kernel 1: zero node accumulator ----------------
__global__ void __launch_bounds__(256) zero_kernel(int n4) {
    int i = blockIdx.x * 256 + threadIdx.x;
    if (i < n4) ((float4*)g_h)[i] = make_float4(0.f, 0.f, 0.f, 0.f);
}

// ---------------- kernel 2: transpose weights into scratch ----------------
__global__ void __launch_bounds__(256) prep_kernel(const float* __restrict__ W_up,
                                                   const float* __restrict__ lins_w) {
    int gid = blockIdx.x * 256 + threadIdx.x;
    if (gid < HIDDEN * OUT_EMB) {
        int k = gid >> 8, c = gid & 255;              // Wt_up[k][c] = W_up[c][k]
        g_wt_up[gid] = W_up[c * HIDDEN + k];
    } else if (gid < HIDDEN * OUT_EMB + 3 * OUT_EMB * OUT_EMB) {
        int g2 = gid - HIDDEN * OUT_EMB;
        int l = g2 >> 16;
        int rem = g2 & 65535;
        int k = rem >> 8, c = rem & 255;              // Wt[l][k][c] = lins[l][c][k]
        g_wt_lins[g2] = lins_w[(size_t)l * 65536 + c * 256 + k];
    }
}

// ---------------- kernel 3: edge compute + scatter (1 warp / edge) ----------------
__global__ void __launch_bounds__(256) edge_kernel(const float* __restrict__ x,
                                                   const float* __restrict__ rbf,
                                                   const int*   __restrict__ ei,
                                                   const float* __restrict__ W_rbf,
                                                   int E, int N) {
    __shared__ float sWt[NUM_RADIAL * HIDDEN];   // transposed: sWt[r][c]
    for (int t = threadIdx.x; t < NUM_RADIAL * HIDDEN; t += 256) {
        int c = t & 127, r = t >> 7;
        sWt[r * HIDDEN + c] = W_rbf[c * NUM_RADIAL + r];
    }
    __syncthreads();

    long long gid = (long long)blockIdx.x * 256 + threadIdx.x;
    int e = (int)(gid >> 5);
    int lane = threadIdx.x & 31;
    if (e >= E) return;

    int node = __ldg(ei + e);
    float rb[NUM_RADIAL];
#pragma unroll
    for (int r = 0; r < NUM_RADIAL; r++) rb[r] = __ldg(rbf + (size_t)e * NUM_RADIAL + r);

    float4 xv = *(const float4*)(x + (size_t)e * HIDDEN + lane * 4);
    float4 p = make_float4(0.f, 0.f, 0.f, 0.f);
#pragma unroll
    for (int r = 0; r < NUM_RADIAL; r++) {
        float4 w = ((const float4*)(sWt + r * HIDDEN))[lane];
        p.x = fmaf(rb[r], w.x, p.x);
        p.y = fmaf(rb[r], w.y, p.y);
        p.z = fmaf(rb[r], w.z, p.z);
        p.w = fmaf(rb[r], w.w, p.w);
    }
    float4 res;
    res.x = p.x * xv.x; res.y = p.y * xv.y; res.z = p.z * xv.z; res.w = p.w * xv.w;

    if (node >= 0 && node < N) {
        atomicAdd((float4*)(g_h + (size_t)node * HIDDEN + lane * 4), res);   // RED.v4 (sm_90+)
    }
}

// ---------------- fused MLP: 64-node tile per CTA, f32x2 register tiling ----------------
// thread grid 8 (rows) x 32 (cols); per-thread tile 8 rows x 8 cols (4 f32x2 col pairs)
template<int K, bool RELU, bool BIAS>
__device__ __forceinline__ void gemm_layer(const float* __restrict__ in,     // smem [64][256]
                                           float* __restrict__ outb,         // smem [64][256]
                                           const float* __restrict__ Wt,     // global [K][256]
                                           const float* __restrict__ bias,   // global [256] or null
                                           float* __restrict__ sW,           // smem [16][256]
                                           int tid) {
    const int tr = tid >> 5;
    const int tc = tid & 31;
    unsigned long long acc[8][4];
#pragma unroll
    for (int r = 0; r < 8; r++)
#pragma unroll
        for (int j = 0; j < 4; j++) acc[r][j] = 0ULL;

    for (int kb = 0; kb < K; kb += 16) {
        __syncthreads();
#pragma unroll
        for (int t = 0; t < 16; t++)
            sW[t * 256 + tid] = Wt[(size_t)(kb + t) * 256 + tid];
        __syncthreads();
#pragma unroll
        for (int k = 0; k < 16; k++) {
            unsigned long long a2[8];
#pragma unroll
            for (int r = 0; r < 8; r++) {
                float a = in[(tr * 8 + r) * 256 + kb + k];
                a2[r] = pack2(a, a);
            }
            unsigned long long w2[4];
#pragma unroll
            for (int j = 0; j < 4; j++)
                w2[j] = *(const unsigned long long*)(sW + k * 256 + tc * 2 + 64 * j);
#pragma unroll
            for (int r = 0; r < 8; r++)
#pragma unroll
                for (int j = 0; j < 4; j++)
                    fma2(acc[r][j], a2[r], w2[j]);
        }
    }

    float2 bb[4];
#pragma unroll
    for (int j = 0; j < 4; j++) {
        if (BIAS) bb[j] = *(const float2*)(bias + tc * 2 + 64 * j);
        else      bb[j] = make_float2(0.f, 0.f);
    }
#pragma unroll
    for (int r = 0; r < 8; r++) {
#pragma unroll
        for (int j = 0; j < 4; j++) {
            float lo, hi;
            unpack2(acc[r][j], lo, hi);
            lo += bb[j].x; hi += bb[j].y;
            if (RELU) { lo = fmaxf(lo, 0.f); hi = fmaxf(hi, 0.f); }
            *(float2*)(outb + (tr * 8 + r) * 256 + tc * 2 + 64 * j) = make_float2(lo, hi);
        }
    }
}

__global__ void __launch_bounds__(256, 1) mlp_kernel(const float* __restrict__ lins_b,
                                                     const float* __restrict__ W_out,
                                                     float* __restrict__ out, int N) {
    extern __shared__ float smem[];
    float* bufA = smem;                   // [64][256]
    float* bufB = smem + 64 * 256;        // [64][256]
    float* sW   = smem + 2 * 64 * 256;    // [16][256]
    const int tid = threadIdx.x;
    const int rowBase = blockIdx.x * 64;

    // load node features [64][128] into bufA (stride 256)
#pragma unroll
    for (int t = 0; t < 8; t++) {
        int idx4 = tid + t * 256;          // 0..2047 : row=idx4/32, c4=idx4%32
        int row = idx4 >> 5;
        int c4 = idx4 & 31;
        float4 v = make_float4(0.f, 0.f, 0.f, 0.f);
        int grow = rowBase + row;
        if (grow < N) v = *(const float4*)(g_h + (size_t)grow * HIDDEN + c4 * 4);
        *(float4*)(bufA + row * 256 + c4 * 4) = v;
    }
    // (gemm_layer begins with __syncthreads())

    gemm_layer<128, false, false>(bufA, bufB, g_wt_up, nullptr, sW, tid);              // up
    gemm_layer<256, true,  true >(bufB, bufA, g_wt_lins,            lins_b,       sW, tid);
    gemm_layer<256, true,  true >(bufA, bufB, g_wt_lins + 65536,    lins_b + 256, sW, tid);
    gemm_layer<256, true,  true >(bufB, bufA, g_wt_lins + 2 * 65536, lins_b + 512, sW, tid);

    __syncthreads();
    if (tid < 256) sW[tid] = W_out[tid];
    __syncthreads();

    // final projection [64][256] x [256] -> [64]; 4 threads per row
    int row = tid >> 2;
    int seg = tid & 3;
    float s = 0.f;
#pragma unroll
    for (int k = 0; k < 64; k++)
        s = fmaf(bufA[row * 256 + seg * 64 + k], sW[seg * 64 + k], s);
    s += __shfl_xor_sync(0xffffffffu, s, 1);
    s += __shfl_xor_sync(0xffffffffu, s, 2);
    int grow = rowBase + row;
    if (seg == 0 && grow < N) out[grow] = s;
}

// ---------------- launch ----------------
extern "C" void kernel_launch(void* const* d_in, const int* in_sizes, int n_in,
                              void* d_out, int out_size) {
    const float* x   = (const float*)d_in[0];
    const float* rbf = (const float*)d_in[1];
    const int*   ei  = (const int*)d_in[2];

    // locate W_rbf robustly (size 128*6=768); num_nodes scalar may or may not be present
    int wi = 3;
    while (wi < n_in && in_sizes[wi] != HIDDEN * NUM_RADIAL) wi++;
    const float* W_rbf  = (const float*)d_in[wi + 0];
    const float* W_up   = (const float*)d_in[wi + 1];
    const float* lins_w = (const float*)d_in[wi + 2];
    const float* lins_b = (const float*)d_in[wi + 3];
    const float* W_out  = (const float*)d_in[wi + 4];
    float* out = (float*)d_out;

    int E = in_sizes[0] / HIDDEN;
    int N = out_size < MAX_NODES ? out_size : MAX_NODES;

    const int SMEM_BYTES = (2 * 64 * 256 + 16 * 256) * (int)sizeof(float);  // 147456
    cudaFuncSetAttribute(mlp_kernel, cudaFuncAttributeMaxDynamicSharedMemorySize, SMEM_BYTES);

    int n4 = N * HIDDEN / 4;
    zero_kernel<<<(n4 + 255) / 256, 256>>>(n4);

    int prep_total = HIDDEN * OUT_EMB + 3 * OUT_EMB * OUT_EMB;
    prep_kernel<<<(prep_total + 255) / 256, 256>>>(W_up, lins_w);

    long long ethreads = (long long)E * 32;
    int eblocks = (int)((ethreads + 255) / 256);
    edge_kernel<<<eblocks, 256>>>(x, rbf, ei, W_rbf, E, N);

    int mblocks = (N + 63) / 64;
    mlp_kernel<<<mblocks, 256, SMEM_BYTES>>>(lins_b, W_out, out, N);
}

// round 2
// speedup vs baseline: 1.0088x; 1.0088x over previous
#include <cuda_runtime.h>
#include <cuda_bf16.h>
#include <cstdint>

// ---------------- problem constants ----------------
#define HIDDEN      128
#define NUM_RADIAL  6
#define OUT_EMB     256
#define MAX_NODES   50000

// ---------------- device scratch (no allocs allowed) ----------------
__device__ float g_h[(size_t)MAX_NODES * HIDDEN];          // node accumulator [N,128]
__device__ float g_wt_up[HIDDEN * OUT_EMB];                // W_up transposed [128][256]
__device__ float g_wt_lins[3 * OUT_EMB * OUT_EMB];         // lins transposed [3][256][256]

// ---------------- f32x2 packed helpers (sm_100+) ----------------
__device__ __forceinline__ unsigned long long pack2(float a, float b) {
    unsigned long long r;
    asm("mov.b64 %0, {%1, %2};" : "=l"(r) : "f"(a), "f"(b));
    return r;
}
__device__ __forceinline__ void unpack2(unsigned long long v, float& a, float& b) {
    asm("mov.b64 {%0, %1}, %2;" : "=f"(a), "=f"(b) : "l"(v));
}
__device__ __forceinline__ void fma2(unsigned long long& d, unsigned long long a, unsigned long long b) {
    asm("fma.rn.f32x2 %0, %1, %2, %0;" : "+l"(d) : "l"(a), "l"(b));
}

// ---------------- kernel 1: zero node accumulator ----------------
__global__ void __launch_bounds__(256) zero_kernel(int n4) {
    int i = blockIdx.x * 256 + threadIdx.x;
    if (i < n4) ((float4*)g_h)[i] = make_float4(0.f, 0.f, 0.f, 0.f);
}

// ---------------- kernel 2: transpose weights into scratch ----------------
__global__ void __launch_bounds__(256) prep_kernel(const float* __restrict__ W_up,
                                                   const float* __restrict__ lins_w) {
    int gid = blockIdx.x * 256 + threadIdx.x;
    if (gid < HIDDEN * OUT_EMB) {
        int k = gid >> 8, c = gid & 255;              // Wt_up[k][c] = W_up[c][k]
        g_wt_up[gid] = W_up[c * HIDDEN + k];
    } else if (gid < HIDDEN * OUT_EMB + 3 * OUT_EMB * OUT_EMB) {
        int g2 = gid - HIDDEN * OUT_EMB;
        int l = g2 >> 16;
        int rem = g2 & 65535;
        int k = rem >> 8, c = rem & 255;              // Wt[l][k][c] = lins[l][c][k]
        g_wt_lins[g2] = lins_w[(size_t)l * 65536 + c * 256 + k];
    }
}

// ---------------- kernel 3: edge compute + scatter (1 warp / edge) ----------------
__global__ void __launch_bounds__(256) edge_kernel(const float* __restrict__ x,
                                                   const float* __restrict__ rbf,
                                                   const int*   __restrict__ ei,
                                                   const float* __restrict__ W_rbf,
                                                   int E, int N) {
    __shared__ float sWt[NUM_RADIAL * HIDDEN];   // transposed: sWt[r][c]
    for (int t = threadIdx.x; t < NUM_RADIAL * HIDDEN; t += 256) {
        int c = t & 127, r = t >> 7;
        sWt[r * HIDDEN + c] = W_rbf[c * NUM_RADIAL + r];
    }
    __syncthreads();

    long long gid = (long long)blockIdx.x * 256 + threadIdx.x;
    int e = (int)(gid >> 5);
    int lane = threadIdx.x & 31;
    if (e >= E) return;

    int node = __ldg(ei + e);
    float rb[NUM_RADIAL];
#pragma unroll
    for (int r = 0; r < NUM_RADIAL; r++) rb[r] = __ldg(rbf + (size_t)e * NUM_RADIAL + r);

    float4 xv = *(const float4*)(x + (size_t)e * HIDDEN + lane * 4);
    float4 p = make_float4(0.f, 0.f, 0.f, 0.f);
#pragma unroll
    for (int r = 0; r < NUM_RADIAL; r++) {
        float4 w = ((const float4*)(sWt + r * HIDDEN))[lane];
        p.x = fmaf(rb[r], w.x, p.x);
        p.y = fmaf(rb[r], w.y, p.y);
        p.z = fmaf(rb[r], w.z, p.z);
        p.w = fmaf(rb[r], w.w, p.w);
    }
    float4 res;
    res.x = p.x * xv.x; res.y = p.y * xv.y; res.z = p.z * xv.z; res.w = p.w * xv.w;

    if (node >= 0 && node < N) {
        atomicAdd((float4*)(g_h + (size_t)node * HIDDEN + lane * 4), res);   // RED.v4
    }
}

// ---------------- fused MLP: 64-node tile / CTA, 512 threads ----------------
// thread grid: tr = tid>>6 (8 row groups x 8 rows), tc = tid&63 (64 col groups x 4 cols)
// per-thread tile: 8 rows x 4 cols (2 f32x2 pairs), double-buffered weight staging.

__device__ __forceinline__ void stage_w(float* __restrict__ dst,
                                        const float* __restrict__ Wt,
                                        int kbase, int tid) {
    // 16 rows x 256 cols, 512 threads -> 8 floats (2 float4) each, coalesced
    int idx = tid * 8;
    int row = idx >> 8;
    int col = idx & 255;
    const float4* src = (const float4*)(Wt + (size_t)(kbase + row) * 256 + col);
    float4 v0 = src[0];
    float4 v1 = src[1];
    *(float4*)(dst + row * 256 + col)     = v0;
    *(float4*)(dst + row * 256 + col + 4) = v1;
}

template<int K, bool RELU, bool BIAS>
__device__ __forceinline__ void gemm_layer(const float* __restrict__ in,    // smem [64][256]
                                           float* __restrict__ outb,        // smem [64][256]
                                           const float* __restrict__ Wt,    // global [K][256]
                                           const float* __restrict__ bias,  // global [256] or null
                                           float* __restrict__ sW0,
                                           float* __restrict__ sW1,
                                           int tid) {
    const int tr = tid >> 6;          // 0..7  -> rows tr*8 .. tr*8+7
    const int tc = tid & 63;          // 0..63 -> col pairs tc*2 and tc*2+128
    unsigned long long acc[8][2];
#pragma unroll
    for (int r = 0; r < 8; r++) { acc[r][0] = 0ULL; acc[r][1] = 0ULL; }

    constexpr int NB = K / 16;
    float* bufs[2] = { sW0, sW1 };

    stage_w(sW0, Wt, 0, tid);
    __syncthreads();

#pragma unroll
    for (int b = 0; b < NB; b++) {
        const float* cw = bufs[b & 1];
        if (b + 1 < NB) stage_w(bufs[(b + 1) & 1], Wt, (b + 1) * 16, tid);
        const int kb = b * 16;
#pragma unroll
        for (int k4 = 0; k4 < 4; k4++) {
            float4 av[8];
#pragma unroll
            for (int r = 0; r < 8; r++)
                av[r] = *(const float4*)(in + (tr * 8 + r) * 256 + kb + k4 * 4);
#pragma unroll
            for (int kk = 0; kk < 4; kk++) {
                const int k = k4 * 4 + kk;
                unsigned long long w0 = *(const unsigned long long*)(cw + k * 256 + tc * 2);
                unsigned long long w1 = *(const unsigned long long*)(cw + k * 256 + tc * 2 + 128);
#pragma unroll
                for (int r = 0; r < 8; r++) {
                    const float* afp = (const float*)&av[r];
                    unsigned long long a2 = pack2(afp[kk], afp[kk]);
                    fma2(acc[r][0], a2, w0);
                    fma2(acc[r][1], a2, w1);
                }
            }
        }
        __syncthreads();   // compute on cw done; next stage into cw is safe
    }

    float2 bb[2];
#pragma unroll
    for (int j = 0; j < 2; j++) {
        if (BIAS) bb[j] = *(const float2*)(bias + tc * 2 + 128 * j);
        else      bb[j] = make_float2(0.f, 0.f);
    }
#pragma unroll
    for (int r = 0; r < 8; r++) {
#pragma unroll
        for (int j = 0; j < 2; j++) {
            float lo, hi;
            unpack2(acc[r][j], lo, hi);
            lo += bb[j].x; hi += bb[j].y;
            if (RELU) { lo = fmaxf(lo, 0.f); hi = fmaxf(hi, 0.f); }
            *(float2*)(outb + (tr * 8 + r) * 256 + tc * 2 + 128 * j) = make_float2(lo, hi);
        }
    }
}

__global__ void __launch_bounds__(512, 1) mlp_kernel(const float* __restrict__ lins_b,
                                                     const float* __restrict__ W_out,
                                                     float* __restrict__ out, int N) {
    extern __shared__ float smem[];
    float* bufA = smem;                        // [64][256]  64 KB
    float* bufB = smem + 64 * 256;             // [64][256]  64 KB
    float* sW0  = smem + 2 * 64 * 256;         // [16][256]  16 KB
    float* sW1  = sW0 + 16 * 256;              // [16][256]  16 KB
    const int tid = threadIdx.x;
    const int rowBase = blockIdx.x * 64;

    // load node features [64][128] into bufA (row stride 256)
#pragma unroll
    for (int t = 0; t < 4; t++) {
        int idx4 = tid + t * 512;          // 0..2047: row=idx4/32, c4=idx4%32
        int row = idx4 >> 5;
        int c4 = idx4 & 31;
        float4 v = make_float4(0.f, 0.f, 0.f, 0.f);
        int grow = rowBase + row;
        if (grow < N) v = *(const float4*)(g_h + (size_t)grow * HIDDEN + c4 * 4);
        *(float4*)(bufA + row * 256 + c4 * 4) = v;
    }
    __syncthreads();

    gemm_layer<128, false, false>(bufA, bufB, g_wt_up, nullptr, sW0, sW1, tid);
    gemm_layer<256, true,  true >(bufB, bufA, g_wt_lins,             lins_b,       sW0, sW1, tid);
    gemm_layer<256, true,  true >(bufA, bufB, g_wt_lins + 65536,     lins_b + 256, sW0, sW1, tid);
    gemm_layer<256, true,  true >(bufB, bufA, g_wt_lins + 2 * 65536, lins_b + 512, sW0, sW1, tid);

    __syncthreads();
    if (tid < 256) sW0[tid] = W_out[tid];
    __syncthreads();

    // final projection [64][256] x [256] -> [64]; 8 threads per row
    int row = tid >> 3;
    int seg = tid & 7;
    float s = 0.f;
#pragma unroll
    for (int k = 0; k < 32; k++)
        s = fmaf(bufA[row * 256 + seg * 32 + k], sW0[seg * 32 + k], s);
    s += __shfl_xor_sync(0xffffffffu, s, 1);
    s += __shfl_xor_sync(0xffffffffu, s, 2);
    s += __shfl_xor_sync(0xffffffffu, s, 4);
    int grow = rowBase + row;
    if (seg == 0 && grow < N) out[grow] = s;
}

// ---------------- launch ----------------
extern "C" void kernel_launch(void* const* d_in, const int* in_sizes, int n_in,
                              void* d_out, int out_size) {
    const float* x   = (const float*)d_in[0];
    const float* rbf = (const float*)d_in[1];
    const int*   ei  = (const int*)d_in[2];

    int wi = 3;
    while (wi < n_in && in_sizes[wi] != HIDDEN * NUM_RADIAL) wi++;
    const float* W_rbf  = (const float*)d_in[wi + 0];
    const float* W_up   = (const float*)d_in[wi + 1];
    const float* lins_w = (const float*)d_in[wi + 2];
    const float* lins_b = (const float*)d_in[wi + 3];
    const float* W_out  = (const float*)d_in[wi + 4];
    float* out = (float*)d_out;

    int E = in_sizes[0] / HIDDEN;
    int N = out_size < MAX_NODES ? out_size : MAX_NODES;

    const int SMEM_BYTES = (2 * 64 * 256 + 2 * 16 * 256) * (int)sizeof(float);  // 163840
    cudaFuncSetAttribute(mlp_kernel, cudaFuncAttributeMaxDynamicSharedMemorySize, SMEM_BYTES);

    int n4 = N * HIDDEN / 4;
    zero_kernel<<<(n4 + 255) / 256, 256>>>(n4);

    int prep_total = HIDDEN * OUT_EMB + 3 * OUT_EMB * OUT_EMB;
    prep_kernel<<<(prep_total + 255) / 256, 256>>>(W_up, lins_w);

    long long ethreads = (long long)E * 32;
    int eblocks = (int)((ethreads + 255) / 256);
    edge_kernel<<<eblocks, 256>>>(x, rbf, ei, W_rbf, E, N);

    int mblocks = (N + 63) / 64;
    mlp_kernel<<<mblocks, 512, SMEM_BYTES>>>(lins_b, W_out, out, N);
}

// round 4
// speedup vs baseline: 1.5260x; 1.5128x over previous
#include <cuda_runtime.h>
#include <cuda_bf16.h>
#include <cstdint>

// ---------------- problem constants ----------------
#define HIDDEN      128
#define NUM_RADIAL  6
#define OUT_EMB     256
#define MAX_NODES   50000

#define AS_STRIDE   260      // 128-row A tile, padded fp32 row stride (bank-safe)
#define WS_STRIDE   36       // W chunk row stride (32 + 4 pad)

// ---------------- device scratch ----------------
__device__ float g_h[(size_t)MAX_NODES * HIDDEN];   // node accumulator [N,128]

// ---------------- helpers ----------------
__device__ __forceinline__ uint32_t smem_u32(const void* p) {
    uint32_t a;
    asm("{ .reg .u64 t; cvta.to.shared.u64 t, %1; cvt.u32.u64 %0, t; }" : "=r"(a) : "l"(p));
    return a;
}
__device__ __forceinline__ uint32_t f2tf(float x) {   // round-to-nearest tf32 (b32 with low 13 bits zero)
    uint32_t r; asm("cvt.rna.tf32.f32 %0, %1;" : "=r"(r) : "f"(x)); return r;
}
__device__ __forceinline__ void mma8(float* d, const uint32_t* a, uint32_t b0, uint32_t b1) {
    asm volatile("mma.sync.aligned.m16n8k8.row.col.f32.tf32.tf32.f32 "
                 "{%0,%1,%2,%3}, {%4,%5,%6,%7}, {%8,%9}, {%0,%1,%2,%3};"
                 : "+f"(d[0]), "+f"(d[1]), "+f"(d[2]), "+f"(d[3])
                 : "r"(a[0]), "r"(a[1]), "r"(a[2]), "r"(a[3]), "r"(b0), "r"(b1));
}
__device__ __forceinline__ void cp16(uint32_t s, const float* g) {
    asm volatile("cp.async.cg.shared.global [%0], [%1], 16;" :: "r"(s), "l"(g));
}
#define CP_COMMIT() asm volatile("cp.async.commit_group;")
#define CP_WAIT(n)  asm volatile("cp.async.wait_group %0;" :: "n"(n))

// ================= kernel 1: zero accumulator =================
__global__ void __launch_bounds__(256) zero_kernel(int n4) {
    int i = blockIdx.x * 256 + threadIdx.x;
    if (i < n4) ((float4*)g_h)[i] = make_float4(0.f, 0.f, 0.f, 0.f);
}

// ================= kernel 2: edge compute + scatter =================
__global__ void __launch_bounds__(256) edge_kernel(const float* __restrict__ x,
                                                   const float* __restrict__ rbf,
                                                   const int*   __restrict__ ei,
                                                   const float* __restrict__ W_rbf,
                                                   int E, int N) {
    __shared__ float sWt[NUM_RADIAL * HIDDEN];
    for (int t = threadIdx.x; t < NUM_RADIAL * HIDDEN; t += 256) {
        int c = t & 127, r = t >> 7;
        sWt[r * HIDDEN + c] = W_rbf[c * NUM_RADIAL + r];
    }
    __syncthreads();

    long long gid = (long long)blockIdx.x * 256 + threadIdx.x;
    int e = (int)(gid >> 5);
    int lane = threadIdx.x & 31;
    if (e >= E) return;

    int node = __ldg(ei + e);
    float rb[NUM_RADIAL];
#pragma unroll
    for (int r = 0; r < NUM_RADIAL; r++) rb[r] = __ldg(rbf + (size_t)e * NUM_RADIAL + r);

    float4 xv = *(const float4*)(x + (size_t)e * HIDDEN + lane * 4);
    float4 p = make_float4(0.f, 0.f, 0.f, 0.f);
#pragma unroll
    for (int r = 0; r < NUM_RADIAL; r++) {
        float4 w = ((const float4*)(sWt + r * HIDDEN))[lane];
        p.x = fmaf(rb[r], w.x, p.x);
        p.y = fmaf(rb[r], w.y, p.y);
        p.z = fmaf(rb[r], w.z, p.z);
        p.w = fmaf(rb[r], w.w, p.w);
    }
    float4 res;
    res.x = p.x * xv.x; res.y = p.y * xv.y; res.z = p.z * xv.z; res.w = p.w * xv.w;

    if (node >= 0 && node < N) {
        atomicAdd((float4*)(g_h + (size_t)node * HIDDEN + lane * 4), res);
    }
}

// ================= MLP via mma.sync tf32 (2-term A split) =================
// CTA: 128 rows x 256 cols; 512 thr = 4(m) x 4(n) warps, warp tile 32x64.
// A fp32 in smem [128][260]; W streamed from global in 32-K chunks (cp.async db).
// MODE: 0 = plain, 1 = bias+relu -> As, 2 = last (bias+relu+dot W_out -> fpart)

template<int K, int MODE>
__device__ __forceinline__ void do_layer(float* __restrict__ As,
                                         const float* __restrict__ W0s,
                                         const float* __restrict__ W1s,
                                         uint32_t w0a, uint32_t w1a,
                                         const float* __restrict__ Wg,
                                         const float* __restrict__ bias,
                                         const float* __restrict__ wout,
                                         float* __restrict__ fpart,
                                         int wm, int wn, int lane, int tid) {
    constexpr int NC = K / 32;
    float d[2][8][4];
#pragma unroll
    for (int m = 0; m < 2; m++)
#pragma unroll
        for (int n = 0; n < 8; n++)
#pragma unroll
            for (int j = 0; j < 4; j++) d[m][n][j] = 0.f;

    // stage chunk 0
    {
#pragma unroll
        for (int i = 0; i < 4; i++) {
            int idx = tid + i * 512;
            int row = idx >> 3, q = idx & 7;
            cp16(w0a + (uint32_t)(row * WS_STRIDE + q * 4) * 4, Wg + (size_t)row * K + q * 4);
        }
        CP_COMMIT();
    }

    for (int c = 0; c < NC; c++) {
        __syncthreads();   // all warps done reading buf (c+1)&1 (chunk c-1)
        if (c + 1 < NC) {
            uint32_t na = ((c + 1) & 1) ? w1a : w0a;
#pragma unroll
            for (int i = 0; i < 4; i++) {
                int idx = tid + i * 512;
                int row = idx >> 3, q = idx & 7;
                cp16(na + (uint32_t)(row * WS_STRIDE + q * 4) * 4,
                     Wg + (size_t)row * K + (c + 1) * 32 + q * 4);
            }
            CP_COMMIT();
            CP_WAIT(1);
        } else {
            CP_WAIT(0);
        }
        __syncthreads();   // chunk c visible to all

        const float* Ws = (c & 1) ? W1s : W0s;
        const int kb0 = c * 32;
#pragma unroll
        for (int k8 = 0; k8 < 4; k8++) {
            const int kb = kb0 + k8 * 8;
            uint32_t ah[2][4], al[2][4];
#pragma unroll
            for (int m = 0; m < 2; m++) {
                int r = wm * 32 + m * 16 + (lane >> 2);
                const float* ap = As + r * AS_STRIDE + kb + (lane & 3);
                float x0 = ap[0];
                float x1 = ap[8 * AS_STRIDE];
                float x2 = ap[4];
                float x3 = ap[8 * AS_STRIDE + 4];
                ah[m][0] = f2tf(x0); ah[m][1] = f2tf(x1);
                ah[m][2] = f2tf(x2); ah[m][3] = f2tf(x3);
                al[m][0] = f2tf(x0 - __uint_as_float(ah[m][0]));
                al[m][1] = f2tf(x1 - __uint_as_float(ah[m][1]));
                al[m][2] = f2tf(x2 - __uint_as_float(ah[m][2]));
                al[m][3] = f2tf(x3 - __uint_as_float(ah[m][3]));
            }
#pragma unroll
            for (int n = 0; n < 8; n++) {
                int coln = wn * 64 + n * 8 + (lane >> 2);
                const float* bp = Ws + coln * WS_STRIDE + k8 * 8 + (lane & 3);
                uint32_t b0 = f2tf(bp[0]);
                uint32_t b1 = f2tf(bp[4]);
#pragma unroll
                for (int m = 0; m < 2; m++) {
                    mma8(d[m][n], ah[m], b0, b1);
                    mma8(d[m][n], al[m], b0, b1);
                }
            }
        }
    }

    if (MODE != 2) {
        __syncthreads();   // all reads of As done before overwrite
#pragma unroll
        for (int m = 0; m < 2; m++) {
            int r = wm * 32 + m * 16 + (lane >> 2);
#pragma unroll
            for (int n = 0; n < 8; n++) {
                int col = wn * 64 + n * 8 + (lane & 3) * 2;
                float v0 = d[m][n][0], v1 = d[m][n][1];
                float v2 = d[m][n][2], v3 = d[m][n][3];
                if (MODE == 1) {
                    float b0 = bias[col], b1 = bias[col + 1];
                    v0 = fmaxf(v0 + b0, 0.f); v1 = fmaxf(v1 + b1, 0.f);
                    v2 = fmaxf(v2 + b0, 0.f); v3 = fmaxf(v3 + b1, 0.f);
                }
                *(float2*)(As + r * AS_STRIDE + col)       = make_float2(v0, v1);
                *(float2*)(As + (r + 8) * AS_STRIDE + col) = make_float2(v2, v3);
            }
        }
        __syncthreads();
    } else {
        float s[2][2] = {{0.f, 0.f}, {0.f, 0.f}};   // [m][row-half]
#pragma unroll
        for (int m = 0; m < 2; m++)
#pragma unroll
            for (int n = 0; n < 8; n++) {
                int col = wn * 64 + n * 8 + (lane & 3) * 2;
                float b0 = bias[col], b1 = bias[col + 1];
                float w0 = wout[col], w1 = wout[col + 1];
                float v0 = fmaxf(d[m][n][0] + b0, 0.f);
                float v1 = fmaxf(d[m][n][1] + b1, 0.f);
                float v2 = fmaxf(d[m][n][2] + b0, 0.f);
                float v3 = fmaxf(d[m][n][3] + b1, 0.f);
                s[m][0] = fmaf(v0, w0, fmaf(v1, w1, s[m][0]));
                s[m][1] = fmaf(v2, w0, fmaf(v3, w1, s[m][1]));
            }
#pragma unroll
        for (int m = 0; m < 2; m++)
#pragma unroll
            for (int h = 0; h < 2; h++) {
                float v = s[m][h];
                v += __shfl_xor_sync(0xffffffffu, v, 1);
                v += __shfl_xor_sync(0xffffffffu, v, 2);
                s[m][h] = v;
            }
        if ((lane & 3) == 0) {
            int rbase = wm * 32 + (lane >> 2);
            fpart[wn * 128 + rbase]      = s[0][0];
            fpart[wn * 128 + rbase + 8]  = s[0][1];
            fpart[wn * 128 + rbase + 16] = s[1][0];
            fpart[wn * 128 + rbase + 24] = s[1][1];
        }
    }
}

// smem float offsets
#define F_AS    0
#define F_W0    33280
#define F_W1    (33280 + 9216)
#define F_BIAS  (33280 + 2 * 9216)
#define F_WOUT  (F_BIAS + 768)
#define F_FPART (F_WOUT + 256)
#define F_TOTAL (F_FPART + 512)        // 53248 floats = 212992 bytes

__global__ void __launch_bounds__(512, 1) mlp_kernel(const float* __restrict__ W_up,
                                                     const float* __restrict__ lins_w,
                                                     const float* __restrict__ lins_b,
                                                     const float* __restrict__ W_out,
                                                     float* __restrict__ out, int N) {
    extern __shared__ float smem[];
    float* As    = smem + F_AS;
    float* W0s   = smem + F_W0;
    float* W1s   = smem + F_W1;
    float* sbias = smem + F_BIAS;
    float* swout = smem + F_WOUT;
    float* fpart = smem + F_FPART;
    uint32_t w0a = smem_u32(W0s), w1a = smem_u32(W1s);

    const int tid = threadIdx.x;
    const int lane = tid & 31;
    const int wid = tid >> 5;
    const int wm = wid & 3;
    const int wn = wid >> 2;
    const int rowBase = blockIdx.x * 128;

    for (int t = tid; t < 768; t += 512) sbias[t] = lins_b[t];
    if (tid < 256) swout[tid] = W_out[tid];

    // load A: g_h[128 rows x 128 cols] fp32
#pragma unroll
    for (int i = 0; i < 8; i++) {
        int idx = tid + i * 512;          // 0..4095
        int row = idx >> 5, c4 = idx & 31;
        float4 v = make_float4(0.f, 0.f, 0.f, 0.f);
        int grow = rowBase + row;
        if (grow < N) v = *(const float4*)(g_h + (size_t)grow * HIDDEN + c4 * 4);
        *(float4*)(As + row * AS_STRIDE + c4 * 4) = v;
    }
    // (first in-loop __syncthreads of do_layer orders these writes vs compute)

    do_layer<128, 0>(As, W0s, W1s, w0a, w1a, W_up,              nullptr,     nullptr, nullptr, wm, wn, lane, tid);
    do_layer<256, 1>(As, W0s, W1s, w0a, w1a, lins_w,            sbias,       nullptr, nullptr, wm, wn, lane, tid);
    do_layer<256, 1>(As, W0s, W1s, w0a, w1a, lins_w + 65536,    sbias + 256, nullptr, nullptr, wm, wn, lane, tid);
    do_layer<256, 2>(As, W0s, W1s, w0a, w1a, lins_w + 2 * 65536, sbias + 512, swout,  fpart,   wm, wn, lane, tid);

    __syncthreads();
    if (tid < 128) {
        float s = fpart[tid] + fpart[tid + 128] + fpart[tid + 256] + fpart[tid + 384];
        int grow = rowBase + tid;
        if (grow < N) out[grow] = s;
    }
}

// ================= launch =================
extern "C" void kernel_launch(void* const* d_in, const int* in_sizes, int n_in,
                              void* d_out, int out_size) {
    const float* x   = (const float*)d_in[0];
    const float* rbf = (const float*)d_in[1];
    const int*   ei  = (const int*)d_in[2];

    int wi = 3;
    while (wi < n_in && in_sizes[wi] != HIDDEN * NUM_RADIAL) wi++;
    const float* W_rbf  = (const float*)d_in[wi + 0];
    const float* W_up   = (const float*)d_in[wi + 1];
    const float* lins_w = (const float*)d_in[wi + 2];
    const float* lins_b = (const float*)d_in[wi + 3];
    const float* W_out  = (const float*)d_in[wi + 4];
    float* out = (float*)d_out;

    int E = in_sizes[0] / HIDDEN;
    int N = out_size < MAX_NODES ? out_size : MAX_NODES;

    const int SMEM_BYTES = F_TOTAL * (int)sizeof(float);   // 212992
    cudaFuncSetAttribute(mlp_kernel, cudaFuncAttributeMaxDynamicSharedMemorySize, SMEM_BYTES);

    int n4 = N * HIDDEN / 4;
    zero_kernel<<<(n4 + 255) / 256, 256>>>(n4);

    long long ethreads = (long long)E * 32;
    int eblocks = (int)((ethreads + 255) / 256);
    edge_kernel<<<eblocks, 256>>>(x, rbf, ei, W_rbf, E, N);

    int mblocks = (N + 127) / 128;
    mlp_kernel<<<mblocks, 512, SMEM_BYTES>>>(W_up, lins_w, lins_b, W_out, out, N);
}

// round 5
// speedup vs baseline: 1.9687x; 1.2901x over previous
#include <cuda_runtime.h>
#include <cuda_bf16.h>
#include <cstdint>

// ---------------- problem constants ----------------
#define HIDDEN      128
#define NUM_RADIAL  6
#define OUT_EMB     256
#define MAX_NODES   50000

#define AS_STRIDE   260      // 128-row A tile, padded fp32 row stride (bank-safe)
#define WS_STRIDE   36       // W chunk row stride (32 + 4 pad)

// ---------------- device scratch ----------------
__device__ float g_h[(size_t)MAX_NODES * HIDDEN];                       // node accumulator [N,128]
__device__ float g_w[HIDDEN * OUT_EMB + 3 * OUT_EMB * OUT_EMB];         // tf32-rounded weights

// ---------------- helpers ----------------
__device__ __forceinline__ uint32_t smem_u32(const void* p) {
    uint32_t a;
    asm("{ .reg .u64 t; cvta.to.shared.u64 t, %1; cvt.u32.u64 %0, t; }" : "=r"(a) : "l"(p));
    return a;
}
__device__ __forceinline__ uint32_t f2tf(float x) {   // round-to-nearest tf32
    uint32_t r; asm("cvt.rna.tf32.f32 %0, %1;" : "=r"(r) : "f"(x)); return r;
}
__device__ __forceinline__ float f2tf_f(float x) { return __uint_as_float(f2tf(x)); }
__device__ __forceinline__ void mma8(float* d, const uint32_t* a, uint32_t b0, uint32_t b1) {
    asm volatile("mma.sync.aligned.m16n8k8.row.col.f32.tf32.tf32.f32 "
                 "{%0,%1,%2,%3}, {%4,%5,%6,%7}, {%8,%9}, {%0,%1,%2,%3};"
                 : "+f"(d[0]), "+f"(d[1]), "+f"(d[2]), "+f"(d[3])
                 : "r"(a[0]), "r"(a[1]), "r"(a[2]), "r"(a[3]), "r"(b0), "r"(b1));
}
__device__ __forceinline__ void cp16(uint32_t s, const float* g) {
    asm volatile("cp.async.cg.shared.global [%0], [%1], 16;" :: "r"(s), "l"(g));
}
#define CP_COMMIT() asm volatile("cp.async.commit_group;")
#define CP_WAIT(n)  asm volatile("cp.async.wait_group %0;" :: "n"(n))

// ================= kernel 1: zero accumulator =================
__global__ void __launch_bounds__(256) zero_kernel(int n4) {
    int i = blockIdx.x * 256 + threadIdx.x;
    if (i < n4) ((float4*)g_h)[i] = make_float4(0.f, 0.f, 0.f, 0.f);
}

// ================= kernel 1b: pre-round weights to tf32 =================
__global__ void __launch_bounds__(256) prep_kernel(const float* __restrict__ W_up,
                                                   const float* __restrict__ lins_w) {
    int gid = blockIdx.x * 256 + threadIdx.x;
    const int NW_UP = HIDDEN * OUT_EMB;
    const int NW_ALL = NW_UP + 3 * OUT_EMB * OUT_EMB;
    if (gid < NW_UP)            g_w[gid] = f2tf_f(W_up[gid]);
    else if (gid < NW_ALL)      g_w[gid] = f2tf_f(lins_w[gid - NW_UP]);
}

// ================= kernel 2: edge compute + scatter =================
__global__ void __launch_bounds__(256) edge_kernel(const float* __restrict__ x,
                                                   const float* __restrict__ rbf,
                                                   const int*   __restrict__ ei,
                                                   const float* __restrict__ W_rbf,
                                                   int E, int N) {
    __shared__ float sWt[NUM_RADIAL * HIDDEN];
    for (int t = threadIdx.x; t < NUM_RADIAL * HIDDEN; t += 256) {
        int c = t & 127, r = t >> 7;
        sWt[r * HIDDEN + c] = W_rbf[c * NUM_RADIAL + r];
    }
    __syncthreads();

    long long gid = (long long)blockIdx.x * 256 + threadIdx.x;
    int e = (int)(gid >> 5);
    int lane = threadIdx.x & 31;
    if (e >= E) return;

    int node = __ldg(ei + e);
    float rb[NUM_RADIAL];
#pragma unroll
    for (int r = 0; r < NUM_RADIAL; r++) rb[r] = __ldg(rbf + (size_t)e * NUM_RADIAL + r);

    float4 xv = *(const float4*)(x + (size_t)e * HIDDEN + lane * 4);
    float4 p = make_float4(0.f, 0.f, 0.f, 0.f);
#pragma unroll
    for (int r = 0; r < NUM_RADIAL; r++) {
        float4 w = ((const float4*)(sWt + r * HIDDEN))[lane];
        p.x = fmaf(rb[r], w.x, p.x);
        p.y = fmaf(rb[r], w.y, p.y);
        p.z = fmaf(rb[r], w.z, p.z);
        p.w = fmaf(rb[r], w.w, p.w);
    }
    float4 res;
    res.x = p.x * xv.x; res.y = p.y * xv.y; res.z = p.z * xv.z; res.w = p.w * xv.w;

    if (node >= 0 && node < N) {
        atomicAdd((float4*)(g_h + (size_t)node * HIDDEN + lane * 4), res);
    }
}

// ================= MLP via mma.sync tf32 (tf32-exact activations) =================
// CTA: 128 rows x 256 cols; 512 thr = 4(m) x 4(n) warps, warp tile 32x64.
// A (tf32-exact fp32) in smem [128][260]; W (pre-rounded) streamed via cp.async db.
// MODE: 0 = round->As, 1 = bias+relu+round->As, 2 = last (bias+relu+dot W_out -> fpart)

template<int K, int MODE>
__device__ __forceinline__ void do_layer(float* __restrict__ As,
                                         const float* __restrict__ W0s,
                                         const float* __restrict__ W1s,
                                         uint32_t w0a, uint32_t w1a,
                                         const float* __restrict__ Wg,
                                         const float* __restrict__ bias,
                                         const float* __restrict__ wout,
                                         float* __restrict__ fpart,
                                         int wm, int wn, int lane, int tid) {
    constexpr int NC = K / 32;
    float d[2][8][4];
#pragma unroll
    for (int m = 0; m < 2; m++)
#pragma unroll
        for (int n = 0; n < 8; n++)
#pragma unroll
            for (int j = 0; j < 4; j++) d[m][n][j] = 0.f;

    // stage chunk 0
    {
#pragma unroll
        for (int i = 0; i < 4; i++) {
            int idx = tid + i * 512;
            int row = idx >> 3, q = idx & 7;
            cp16(w0a + (uint32_t)(row * WS_STRIDE + q * 4) * 4, Wg + (size_t)row * K + q * 4);
        }
        CP_COMMIT();
    }

    for (int c = 0; c < NC; c++) {
        __syncthreads();   // all warps done reading buf (c+1)&1 (chunk c-1)
        if (c + 1 < NC) {
            uint32_t na = ((c + 1) & 1) ? w1a : w0a;
#pragma unroll
            for (int i = 0; i < 4; i++) {
                int idx = tid + i * 512;
                int row = idx >> 3, q = idx & 7;
                cp16(na + (uint32_t)(row * WS_STRIDE + q * 4) * 4,
                     Wg + (size_t)row * K + (c + 1) * 32 + q * 4);
            }
            CP_COMMIT();
            CP_WAIT(1);
        } else {
            CP_WAIT(0);
        }
        __syncthreads();   // chunk c visible to all

        const float* Ws = (c & 1) ? W1s : W0s;
        const int kb0 = c * 32;
#pragma unroll
        for (int k8 = 0; k8 < 4; k8++) {
            const int kb = kb0 + k8 * 8;
            uint32_t ah[2][4];
#pragma unroll
            for (int m = 0; m < 2; m++) {
                int r = wm * 32 + m * 16 + (lane >> 2);
                const float* ap = As + r * AS_STRIDE + kb + (lane & 3);
                ah[m][0] = __float_as_uint(ap[0]);
                ah[m][1] = __float_as_uint(ap[8 * AS_STRIDE]);
                ah[m][2] = __float_as_uint(ap[4]);
                ah[m][3] = __float_as_uint(ap[8 * AS_STRIDE + 4]);
            }
#pragma unroll
            for (int n = 0; n < 8; n++) {
                int coln = wn * 64 + n * 8 + (lane >> 2);
                const float* bp = Ws + coln * WS_STRIDE + k8 * 8 + (lane & 3);
                uint32_t b0 = __float_as_uint(bp[0]);
                uint32_t b1 = __float_as_uint(bp[4]);
#pragma unroll
                for (int m = 0; m < 2; m++)
                    mma8(d[m][n], ah[m], b0, b1);
            }
        }
    }

    if (MODE != 2) {
        __syncthreads();   // all reads of As done before overwrite
#pragma unroll
        for (int m = 0; m < 2; m++) {
            int r = wm * 32 + m * 16 + (lane >> 2);
#pragma unroll
            for (int n = 0; n < 8; n++) {
                int col = wn * 64 + n * 8 + (lane & 3) * 2;
                float v0 = d[m][n][0], v1 = d[m][n][1];
                float v2 = d[m][n][2], v3 = d[m][n][3];
                if (MODE == 1) {
                    float b0 = bias[col], b1 = bias[col + 1];
                    v0 = fmaxf(v0 + b0, 0.f); v1 = fmaxf(v1 + b1, 0.f);
                    v2 = fmaxf(v2 + b0, 0.f); v3 = fmaxf(v3 + b1, 0.f);
                }
                v0 = f2tf_f(v0); v1 = f2tf_f(v1); v2 = f2tf_f(v2); v3 = f2tf_f(v3);
                *(float2*)(As + r * AS_STRIDE + col)       = make_float2(v0, v1);
                *(float2*)(As + (r + 8) * AS_STRIDE + col) = make_float2(v2, v3);
            }
        }
        __syncthreads();
    } else {
        float s[2][2] = {{0.f, 0.f}, {0.f, 0.f}};   // [m][row-half]
#pragma unroll
        for (int m = 0; m < 2; m++)
#pragma unroll
            for (int n = 0; n < 8; n++) {
                int col = wn * 64 + n * 8 + (lane & 3) * 2;
                float b0 = bias[col], b1 = bias[col + 1];
                float w0 = wout[col], w1 = wout[col + 1];
                float v0 = fmaxf(d[m][n][0] + b0, 0.f);
                float v1 = fmaxf(d[m][n][1] + b1, 0.f);
                float v2 = fmaxf(d[m][n][2] + b0, 0.f);
                float v3 = fmaxf(d[m][n][3] + b1, 0.f);
                s[m][0] = fmaf(v0, w0, fmaf(v1, w1, s[m][0]));
                s[m][1] = fmaf(v2, w0, fmaf(v3, w1, s[m][1]));
            }
#pragma unroll
        for (int m = 0; m < 2; m++)
#pragma unroll
            for (int h = 0; h < 2; h++) {
                float v = s[m][h];
                v += __shfl_xor_sync(0xffffffffu, v, 1);
                v += __shfl_xor_sync(0xffffffffu, v, 2);
                s[m][h] = v;
            }
        if ((lane & 3) == 0) {
            int rbase = wm * 32 + (lane >> 2);
            fpart[wn * 128 + rbase]      = s[0][0];
            fpart[wn * 128 + rbase + 8]  = s[0][1];
            fpart[wn * 128 + rbase + 16] = s[1][0];
            fpart[wn * 128 + rbase + 24] = s[1][1];
        }
    }
}

// smem float offsets
#define F_AS    0
#define F_W0    33280
#define F_W1    (33280 + 9216)
#define F_BIAS  (33280 + 2 * 9216)
#define F_WOUT  (F_BIAS + 768)
#define F_FPART (F_WOUT + 256)
#define F_TOTAL (F_FPART + 512)        // 53248 floats = 212992 bytes

__global__ void __launch_bounds__(512, 1) mlp_kernel(const float* __restrict__ lins_b,
                                                     const float* __restrict__ W_out,
                                                     float* __restrict__ out, int N) {
    extern __shared__ float smem[];
    float* As    = smem + F_AS;
    float* W0s   = smem + F_W0;
    float* W1s   = smem + F_W1;
    float* sbias = smem + F_BIAS;
    float* swout = smem + F_WOUT;
    float* fpart = smem + F_FPART;
    uint32_t w0a = smem_u32(W0s), w1a = smem_u32(W1s);

    const int tid = threadIdx.x;
    const int lane = tid & 31;
    const int wid = tid >> 5;
    const int wm = wid & 3;
    const int wn = wid >> 2;
    const int rowBase = blockIdx.x * 128;

    for (int t = tid; t < 768; t += 512) sbias[t] = lins_b[t];
    if (tid < 256) swout[tid] = W_out[tid];

    // load A: g_h[128 rows x 128 cols], round to tf32-exact
#pragma unroll
    for (int i = 0; i < 8; i++) {
        int idx = tid + i * 512;          // 0..4095
        int row = idx >> 5, c4 = idx & 31;
        float4 v = make_float4(0.f, 0.f, 0.f, 0.f);
        int grow = rowBase + row;
        if (grow < N) v = *(const float4*)(g_h + (size_t)grow * HIDDEN + c4 * 4);
        v.x = f2tf_f(v.x); v.y = f2tf_f(v.y); v.z = f2tf_f(v.z); v.w = f2tf_f(v.w);
        *(float4*)(As + row * AS_STRIDE + c4 * 4) = v;
    }
    // (first in-loop __syncthreads of do_layer orders these writes vs compute)

    const float* w_up  = g_w;
    const float* w_lin = g_w + HIDDEN * OUT_EMB;

    do_layer<128, 0>(As, W0s, W1s, w0a, w1a, w_up,              nullptr,     nullptr, nullptr, wm, wn, lane, tid);
    do_layer<256, 1>(As, W0s, W1s, w0a, w1a, w_lin,             sbias,       nullptr, nullptr, wm, wn, lane, tid);
    do_layer<256, 1>(As, W0s, W1s, w0a, w1a, w_lin + 65536,     sbias + 256, nullptr, nullptr, wm, wn, lane, tid);
    do_layer<256, 2>(As, W0s, W1s, w0a, w1a, w_lin + 2 * 65536, sbias + 512, swout,   fpart,   wm, wn, lane, tid);

    __syncthreads();
    if (tid < 128) {
        float s = fpart[tid] + fpart[tid + 128] + fpart[tid + 256] + fpart[tid + 384];
        int grow = rowBase + tid;
        if (grow < N) out[grow] = s;
    }
}

// ================= launch =================
extern "C" void kernel_launch(void* const* d_in, const int* in_sizes, int n_in,
                              void* d_out, int out_size) {
    const float* x   = (const float*)d_in[0];
    const float* rbf = (const float*)d_in[1];
    const int*   ei  = (const int*)d_in[2];

    int wi = 3;
    while (wi < n_in && in_sizes[wi] != HIDDEN * NUM_RADIAL) wi++;
    const float* W_rbf  = (const float*)d_in[wi + 0];
    const float* W_up   = (const float*)d_in[wi + 1];
    const float* lins_w = (const float*)d_in[wi + 2];
    const float* lins_b = (const float*)d_in[wi + 3];
    const float* W_out  = (const float*)d_in[wi + 4];
    float* out = (float*)d_out;

    int E = in_sizes[0] / HIDDEN;
    int N = out_size < MAX_NODES ? out_size : MAX_NODES;

    const int SMEM_BYTES = F_TOTAL * (int)sizeof(float);   // 212992
    cudaFuncSetAttribute(mlp_kernel, cudaFuncAttributeMaxDynamicSharedMemorySize, SMEM_BYTES);

    int n4 = N * HIDDEN / 4;
    zero_kernel<<<(n4 + 255) / 256, 256>>>(n4);

    int prep_total = HIDDEN * OUT_EMB + 3 * OUT_EMB * OUT_EMB;
    prep_kernel<<<(prep_total + 255) / 256, 256>>>(W_up, lins_w);

    long long ethreads = (long long)E * 32;
    int eblocks = (int)((ethreads + 255) / 256);
    edge_kernel<<<eblocks, 256>>>(x, rbf, ei, W_rbf, E, N);

    int mblocks = (N + 127) / 128;
    mlp_kernel<<<mblocks, 512, SMEM_BYTES>>>(lins_b, W_out, out, N);
}